// round 3
// baseline (speedup 1.0000x reference)
#include <cuda_runtime.h>
#include <cstdint>
#include <cstddef>
#include <climits>

#define NPTS     8192
#define BATCH    8
#define MSEL     4096        // ceil(0.5 * 8192)
#define NTHREADS 1024
#define PPT      8           // points per thread
// smem: points [NPTS*3] + warp maxima [32] + warp idx [32] + broadcast [4]
#define SMEM_FLOATS (NPTS * 3 + 32 + 32 + 4)
#define SMEM_BYTES  (SMEM_FLOATS * 4)

// Selected indices, produced by FPS kernel, consumed by gather kernel.
__device__ int g_sel_idx[BATCH * MSEL];

// ---------------- f32x2 packed helpers (sm_100+) ----------------
__device__ __forceinline__ unsigned long long pack2(float lo, float hi) {
    unsigned long long r;
    asm("mov.b64 %0, {%1, %2};" : "=l"(r) : "f"(lo), "f"(hi));
    return r;
}
__device__ __forceinline__ void unpack2(unsigned long long v, float& lo, float& hi) {
    asm("mov.b64 {%0, %1}, %2;" : "=f"(lo), "=f"(hi) : "l"(v));
}
__device__ __forceinline__ unsigned long long add2(unsigned long long a, unsigned long long b) {
    unsigned long long r;
    asm("add.rn.f32x2 %0, %1, %2;" : "=l"(r) : "l"(a), "l"(b));
    return r;
}
__device__ __forceinline__ unsigned long long mul2(unsigned long long a, unsigned long long b) {
    unsigned long long r;
    asm("mul.rn.f32x2 %0, %1, %2;" : "=l"(r) : "l"(a), "l"(b));
    return r;
}

extern __shared__ float smem[];

// ---------------- FPS kernel: one CTA per batch ----------------
__global__ __launch_bounds__(NTHREADS, 1)
void fps_kernel(const float* __restrict__ points, float* __restrict__ dp_out)
{
    float*    s_pts   = smem;                       // [NPTS*3] flat xyzxyz...
    unsigned* s_wmax  = (unsigned*)(smem + NPTS * 3);       // [32] per-warp max (uint bits)
    int*      s_widx  = (int*)(smem + NPTS * 3 + 32);       // [32] per-warp min cand idx
    float*    s_bc    = smem + NPTS * 3 + 64;               // [4] broadcast x,y,z,pad

    const int b   = blockIdx.x;
    const int tid = threadIdx.x;
    const float* p = points + (size_t)b * NPTS * 3;

    // Stage points to shared (coalesced).
    for (int k = tid; k < NPTS * 3; k += NTHREADS) s_pts[k] = p[k];
    __syncthreads();

    // Register-resident points: pair j holds ids (2j)*1024+tid (lo) and (2j+1)*1024+tid (hi).
    unsigned long long X[PPT / 2], Y[PPT / 2], Z[PPT / 2];
    float mind[PPT];
#pragma unroll
    for (int i = 0; i < PPT; i++) mind[i] = 1e10f;
#pragma unroll
    for (int j = 0; j < PPT / 2; j++) {
        int i0 = (2 * j) * NTHREADS + tid;
        int i1 = (2 * j + 1) * NTHREADS + tid;
        X[j] = pack2(s_pts[3 * i0 + 0], s_pts[3 * i1 + 0]);
        Y[j] = pack2(s_pts[3 * i0 + 1], s_pts[3 * i1 + 1]);
        Z[j] = pack2(s_pts[3 * i0 + 2], s_pts[3 * i1 + 2]);
    }

    // Step 0: deterministic start at index 0.
    if (tid == 0) {
        s_bc[0] = s_pts[0];
        s_bc[1] = s_pts[1];
        s_bc[2] = s_pts[2];
        s_bc[3] = 0.0f;
        g_sel_idx[b * MSEL + 0] = 0;
        size_t o = (size_t)b * MSEL * 3;
        dp_out[o + 0] = s_pts[0];
        dp_out[o + 1] = s_pts[1];
        dp_out[o + 2] = s_pts[2];
    }
    __syncthreads();

    for (int step = 1; step < MSEL; ++step) {
        // Broadcast last selected point (single LDS.128).
        float4 bc = *(const float4*)s_bc;
        unsigned long long nlx = pack2(-bc.x, -bc.x);
        unsigned long long nly = pack2(-bc.y, -bc.y);
        unsigned long long nlz = pack2(-bc.z, -bc.z);

        // XLA-exact arithmetic: every op individually rounded, no FMA:
        //   d = ((dx*dx + dy*dy) + dz*dz)
        float vmax = 0.0f;
#pragma unroll
        for (int j = 0; j < PPT / 2; j++) {
            unsigned long long dx = add2(X[j], nlx);
            unsigned long long dy = add2(Y[j], nly);
            unsigned long long dz = add2(Z[j], nlz);
            unsigned long long sx = mul2(dx, dx);
            unsigned long long sy = mul2(dy, dy);
            unsigned long long sz = mul2(dz, dz);
            unsigned long long dd = add2(add2(sx, sy), sz);
            float d0, d1;
            unpack2(dd, d0, d1);
            mind[2 * j]     = fminf(mind[2 * j], d0);
            mind[2 * j + 1] = fminf(mind[2 * j + 1], d1);
            vmax = fmaxf(vmax, mind[2 * j]);
            vmax = fmaxf(vmax, mind[2 * j + 1]);
        }

        // Stage A (all warps): warp max value + lowest tied index within warp.
        unsigned vb   = __float_as_uint(vmax);  // nonneg floats: uint order == float order
        unsigned wmax = __reduce_max_sync(0xffffffffu, vb);
        int cand = INT_MAX;
        if (vb == wmax) {
#pragma unroll
            for (int i = PPT - 1; i >= 0; i--)
                if (__float_as_uint(mind[i]) == vb) cand = i * NTHREADS + tid;
        }
        int wmin_idx = __reduce_min_sync(0xffffffffu, cand);
        if ((tid & 31) == 0) {
            s_wmax[tid >> 5] = wmax;
            s_widx[tid >> 5] = wmin_idx;
        }
        __syncthreads();  // bar 1: warp results visible

        // Stage B (warp 0 only): cross-warp max + lowest tied global index.
        if (tid < 32) {
            unsigned wv   = s_wmax[tid];
            unsigned gmax = __reduce_max_sync(0xffffffffu, wv);
            int c2   = (wv == gmax) ? s_widx[tid] : INT_MAX;
            int gidx = __reduce_min_sync(0xffffffffu, c2);
            if (tid == 0) {
                float cx = s_pts[3 * gidx + 0];
                float cy = s_pts[3 * gidx + 1];
                float cz = s_pts[3 * gidx + 2];
                s_bc[0] = cx;
                s_bc[1] = cy;
                s_bc[2] = cz;
                g_sel_idx[b * MSEL + step] = gidx;
                size_t o = ((size_t)b * MSEL + step) * 3;
                dp_out[o + 0] = cx;
                dp_out[o + 1] = cy;
                dp_out[o + 2] = cz;
            }
        }
        __syncthreads();  // bar 2: s_bc ready for next iteration
    }
}

// ---------------- Feature gather: [B, m, 256] float32 ----------------
__global__ void gather_kernel(const float* __restrict__ feat, float* __restrict__ df_out)
{
    // 256 threads/block -> 4 rows/block, 64 threads (float4 x 64 = 256 floats) per row.
    int r = blockIdx.x * 4 + (threadIdx.x >> 6);
    int c = threadIdx.x & 63;
    int b = r >> 12;  // r / 4096
    int id = g_sel_idx[r];
    const float4* src = (const float4*)(feat + ((size_t)b * NPTS + id) * 256);
    float4 v = src[c];
    ((float4*)df_out)[(size_t)r * 64 + c] = v;
}

extern "C" void kernel_launch(void* const* d_in, const int* in_sizes, int n_in,
                              void* d_out, int out_size)
{
    (void)n_in; (void)out_size;
    const float* points;
    const float* feats;
    if (in_sizes[0] == BATCH * NPTS * 3) {
        points = (const float*)d_in[0];
        feats  = (const float*)d_in[1];
    } else {
        points = (const float*)d_in[1];
        feats  = (const float*)d_in[0];
    }

    float* out = (float*)d_out;
    float* dp  = out;                              // [B, m, 3]
    float* df  = out + (size_t)BATCH * MSEL * 3;   // [B, m, 256]

    cudaFuncSetAttribute(fps_kernel, cudaFuncAttributeMaxDynamicSharedMemorySize,
                         SMEM_BYTES);
    fps_kernel<<<BATCH, NTHREADS, SMEM_BYTES>>>(points, dp);
    gather_kernel<<<(BATCH * MSEL) / 4, 256>>>(feats, df);
}